// round 14
// baseline (speedup 1.0000x reference)
#include <cuda_runtime.h>
#include <math.h>
#include <stdint.h>
#include <mma.h>

using namespace nvcuda;

// Problem constants (fixed shapes)
#define B_  16
#define T_  1000
#define TT_ 2000
#define F_  512
#define H_  512
#define HH_ 1024

// ---------------- device scratch ----------------
__device__ float g_wzh [B_ * TT_ * HH_];   // x_cat @ (scale.*[Wz;Wh])^T (bias added in scan)
__device__ float g_hseq[B_ * TT_ * H_ ];
__device__ float g_ln  [B_ * T_  * HH_];
__device__ float g_scale[HH_];
__device__ float g_bias [HH_];
__device__ __align__(16) unsigned long long g_mail[2][8][1024];

// ---------------- packed fp32x2 FMA ----------------
__device__ __forceinline__ float2 ffma2(float2 a, float2 b, float2 c) {
    float2 d;
    asm("fma.rn.f32x2 %0, %1, %2, %3;"
        : "=l"(reinterpret_cast<unsigned long long &>(d))
        : "l"(reinterpret_cast<unsigned long long &>(a)),
          "l"(reinterpret_cast<unsigned long long &>(b)),
          "l"(reinterpret_cast<unsigned long long &>(c)));
    return d;
}

__device__ __forceinline__ float4 tf32x4(float4 v) {
    v.x = wmma::__float_to_tf32(v.x);
    v.y = wmma::__float_to_tf32(v.y);
    v.z = wmma::__float_to_tf32(v.z);
    v.w = wmma::__float_to_tf32(v.w);
    return v;
}

// ---------------- prep ----------------
__global__ void prep_kernel(const float* __restrict__ bz, const float* __restrict__ bh,
                            const float* __restrict__ zg, const float* __restrict__ zb,
                            const float* __restrict__ zm, const float* __restrict__ zv,
                            const float* __restrict__ hg, const float* __restrict__ hb,
                            const float* __restrict__ hm, const float* __restrict__ hv) {
    int n = threadIdx.x;  // 1024 threads
    float sc, bi;
    if (n < 512) {
        sc = zg[n] * rsqrtf(zv[n] + 1e-5f);
        bi = (bz[n] - zm[n]) * sc + zb[n];
    } else {
        int j = n - 512;
        sc = hg[j] * rsqrtf(hv[j] + 1e-5f);
        bi = (bh[j] - hm[j]) * sc + hb[j];
    }
    g_scale[n] = sc;
    g_bias[n]  = bi;
    unsigned long long* mp = &g_mail[0][0][0];
    for (int i = n; i < 2 * 8 * 1024; i += 1024) mp[i] = 0ull;
}

__global__ void dummy_kernel() {}
__global__ void dummy_kernel2() {}

// ================= tiled tf32 GEMM core, 128x128 block, K-stage 32 =================
// 256 threads, warps 4m x 2n, warp tile 32x64 (c_frag[2][4]), double-buffered.
// Dynamic smem: As[2][128][36] + Bs[2][128][36] = 73728 bytes.
#define GEMM_SMEM_DYN 73728
#define LDP 36   // padded row length (floats) for a 32-float K-slab

#define GEMM_BODY128(K, BSCALE)                                                          \
    extern __shared__ __align__(16) float smraw[];                                       \
    float* As0 = smraw;                                                                  \
    float* As1 = smraw + 128 * LDP;                                                      \
    float* Bs0 = smraw + 2 * 128 * LDP;                                                  \
    float* Bs1 = smraw + 3 * 128 * LDP;                                                  \
    int a_r = tid >> 1;                                                                  \
    int a_k = (tid & 1) * 16;                                                            \
    int mw  = (wid & 3) * 32;                                                            \
    int nw  = (wid >> 2) * 64;                                                           \
    wmma::fragment<wmma::accumulator, 16, 16, 8, float> c_frag[2][4];                    \
    _Pragma("unroll")                                                                    \
    for (int mi = 0; mi < 2; mi++)                                                       \
        _Pragma("unroll")                                                                \
        for (int ni = 0; ni < 4; ni++) wmma::fill_fragment(c_frag[mi][ni], 0.f);         \
    float4 pa[4], pb[4];                                                                 \
    _Pragma("unroll")                                                                    \
    for (int u = 0; u < 4; u++) {                                                        \
        pa[u] = *(const float4*)(arow + a_k + 4 * u);                                    \
        pb[u] = *(const float4*)(brow + a_k + 4 * u);                                    \
        pb[u].x *= (BSCALE); pb[u].y *= (BSCALE); pb[u].z *= (BSCALE); pb[u].w *= (BSCALE); \
        *(float4*)(As0 + a_r * LDP + a_k + 4 * u) = tf32x4(pa[u]);                       \
        *(float4*)(Bs0 + a_r * LDP + a_k + 4 * u) = tf32x4(pb[u]);                       \
    }                                                                                    \
    __syncthreads();                                                                     \
    const int S = (K) / 32;                                                              \
    for (int s = 0; s < S; s++) {                                                        \
        float* Ac = (s & 1) ? As1 : As0;                                                 \
        float* Bc = (s & 1) ? Bs1 : Bs0;                                                 \
        if (s + 1 < S) {                                                                 \
            int k0 = (s + 1) * 32;                                                       \
            _Pragma("unroll")                                                            \
            for (int u = 0; u < 4; u++) {                                                \
                pa[u] = *(const float4*)(arow + k0 + a_k + 4 * u);                       \
                pb[u] = *(const float4*)(brow + k0 + a_k + 4 * u);                       \
            }                                                                            \
        }                                                                                \
        _Pragma("unroll")                                                                \
        for (int kk = 0; kk < 32; kk += 8) {                                             \
            wmma::fragment<wmma::matrix_b, 16, 16, 8, wmma::precision::tf32,             \
                           wmma::col_major> b_frag[4];                                   \
            _Pragma("unroll")                                                            \
            for (int ni = 0; ni < 4; ni++)                                               \
                wmma::load_matrix_sync(b_frag[ni], Bc + (nw + 16 * ni) * LDP + kk, LDP); \
            _Pragma("unroll")                                                            \
            for (int mi = 0; mi < 2; mi++) {                                             \
                wmma::fragment<wmma::matrix_a, 16, 16, 8, wmma::precision::tf32,         \
                               wmma::row_major> a_frag;                                  \
                wmma::load_matrix_sync(a_frag, Ac + (mw + 16 * mi) * LDP + kk, LDP);     \
                _Pragma("unroll")                                                        \
                for (int ni = 0; ni < 4; ni++)                                           \
                    wmma::mma_sync(c_frag[mi][ni], a_frag, b_frag[ni], c_frag[mi][ni]);  \
            }                                                                            \
        }                                                                                \
        if (s + 1 < S) {                                                                 \
            float* An = (s & 1) ? As0 : As1;                                             \
            float* Bn = (s & 1) ? Bs0 : Bs1;                                             \
            _Pragma("unroll")                                                            \
            for (int u = 0; u < 4; u++) {                                                \
                pb[u].x *= (BSCALE); pb[u].y *= (BSCALE); pb[u].z *= (BSCALE); pb[u].w *= (BSCALE); \
                *(float4*)(An + a_r * LDP + a_k + 4 * u) = tf32x4(pa[u]);                \
                *(float4*)(Bn + a_r * LDP + a_k + 4 * u) = tf32x4(pb[u]);                \
            }                                                                            \
        }                                                                                \
        __syncthreads();                                                                 \
    }

// ---------------- phase 1: wzh_scaled = x_cat @ (scale .* [Wz;Wh])^T ----------------
__global__ __launch_bounds__(256, 2) void gemm_wzh(const float* __restrict__ x,
                                                   const float* __restrict__ Wz,
                                                   const float* __restrict__ Wh) {
    int tid = threadIdx.x;
    int wid = tid >> 5;
    int m0 = blockIdx.y * 128, n0 = blockIdx.x * 128;

    int m = m0 + (tid >> 1);
    int b = m / TT_;
    int tp = m - b * TT_;
    const float* arow = (tp < T_) ? (x + ((size_t)(b * T_ + tp) << 9))
                                  : (x + ((size_t)((15 - b) * T_ + (tp - T_)) << 9));
    int n = n0 + (tid >> 1);
    const float* brow = (n < 512) ? (Wz + ((size_t)n << 9))
                                  : (Wh + ((size_t)(n - 512) << 9));
    float bscale = g_scale[n];

    GEMM_BODY128(512, bscale)

#pragma unroll
    for (int mi = 0; mi < 2; mi++)
#pragma unroll
        for (int ni = 0; ni < 4; ni++)
            wmma::store_matrix_sync(
                g_wzh + (size_t)(m0 + mw + 16 * mi) * HH_ + n0 + nw + 16 * ni,
                c_frag[mi][ni], HH_, wmma::mem_row_major);
}

// ---------------- phase 2: persistent scan (publish reordered first) ----------------
__global__ __launch_bounds__(512, 1) void scan_kernel(const float* __restrict__ U) {
    __shared__ __align__(16) float h_sm[2][512];
    __shared__ float red[2][2][8][64];

    int t   = threadIdx.x;
    int grp = blockIdx.x >> 4;
    int ci  = blockIdx.x & 15;
    int b0  = grp * 2;

    int r = t & 63;
    int c = t >> 6;
    int urow = (r < 32) ? (ci * 32 + r) : (512 + ci * 32 + (r - 32));

    const float2* Up = (const float2*)(U + (size_t)urow * 512 + c * 64);
    float2 Ureg[32];
#pragma unroll
    for (int q = 0; q < 32; q++) Ureg[q] = __ldg(&Up[q]);

    for (int idx = t; idx < 1024; idx += 512) ((float*)h_sm)[idx] = 0.f;

    int bb = t >> 5, j = t & 31;
    int bcur = b0 + bb;
    int cz = ci * 32 + j, ch = 512 + ci * 32 + j;
    float nz = 0.f, nh = 0.f;
    float hp = 0.f;
    float bzr = 0.f, bhr = 0.f;
    if (t < 64) {
        bzr = g_bias[cz];
        bhr = g_bias[ch];
        nz = __ldg(&g_wzh[(size_t)bcur * TT_ * HH_ + cz]) + bzr;
        nh = __ldg(&g_wzh[(size_t)bcur * TT_ * HH_ + ch]) + bhr;
    }
    int ds    = c * 128 + 2 * (t & 63);
    int dbb   = (ds >> 5) & 1;
    int hbase = ((ds >> 6) << 5) | (ds & 31);
    __syncthreads();

    for (int s = 0; s < TT_; s++) {
        int par2 = s & 1;
        float2 a0 = make_float2(0.f, 0.f), a1 = make_float2(0.f, 0.f);
        {
            const float4* h0 = (const float4*)&h_sm[0][c * 64];
            const float4* h1 = (const float4*)&h_sm[1][c * 64];
#pragma unroll
            for (int q = 0; q < 16; q++) {
                float4 v0 = h0[q];
                float4 v1 = h1[q];
                a0 = ffma2(Ureg[2 * q],     make_float2(v0.x, v0.y), a0);
                a0 = ffma2(Ureg[2 * q + 1], make_float2(v0.z, v0.w), a0);
                a1 = ffma2(Ureg[2 * q],     make_float2(v1.x, v1.y), a1);
                a1 = ffma2(Ureg[2 * q + 1], make_float2(v1.z, v1.w), a1);
            }
        }
        red[par2][0][c][r] = a0.x + a0.y;
        red[par2][1][c][r] = a1.x + a1.y;
        __syncthreads();

        unsigned tag = (unsigned)(s + 1);
        int par = (s + 1) & 1;

        if (t < 64) {
            float uz = 0.f, uh = 0.f;
#pragma unroll
            for (int cc = 0; cc < 8; cc++) {
                uz += red[par2][bb][cc][j];
                uh += red[par2][bb][cc][32 + j];
            }
            float zt = __fdividef(1.f, 1.f + __expf(-(nz + uz)));
            float hc = fmaxf(nh + uh, 0.f);
            float hn = zt * hp + (1.f - zt) * hc;
            hp = hn;
            if (s + 1 < TT_) {
                // mailbox packet FIRST (critical path), hseq store after
                unsigned long long pkt =
                    ((unsigned long long)tag << 32) | (unsigned long long)__float_as_uint(hn);
                asm volatile("st.relaxed.gpu.u64 [%0], %1;"
                             :: "l"(&g_mail[par][grp][ci * 64 + t]), "l"(pkt) : "memory");
            }
            __stcg(&g_hseq[((size_t)bcur * TT_ + s) * H_ + ci * 32 + j], hn);
            if (s + 1 < TT_) {
                nz = __ldg(&g_wzh[((size_t)bcur * TT_ + s + 1) * HH_ + cz]) + bzr;
                nh = __ldg(&g_wzh[((size_t)bcur * TT_ + s + 1) * HH_ + ch]) + bhr;
            }
        }

        if (s + 1 < TT_) {
            const unsigned long long* p = &g_mail[par][grp][ds];
            unsigned long long v0, v1;
            do {
                asm volatile("ld.relaxed.gpu.v2.u64 {%0, %1}, [%2];"
                             : "=l"(v0), "=l"(v1) : "l"(p) : "memory");
            } while (((unsigned)(v0 >> 32) < tag) || ((unsigned)(v1 >> 32) < tag));
            h_sm[dbb][hbase]     = __uint_as_float((unsigned)v0);
            h_sm[dbb][hbase + 1] = __uint_as_float((unsigned)v1);
            asm volatile("bar.sync %0, %1;" :: "r"(c + 1), "r"(64) : "memory");
        }
    }
}

// ---------------- phase 3: LayerNorm (unchanged) ----------------
__global__ __launch_bounds__(256) void ln_kernel(const float* __restrict__ lng,
                                                 const float* __restrict__ lnb) {
    __shared__ float s_sum[8], s_sq[8];
    int row = blockIdx.x;
    int b = row / T_, tt = row - b * T_;
    int tid = threadIdx.x;
    int d = tid * 4;
    const float* base = (d < 512)
        ? (g_hseq + ((size_t)b * TT_ + tt) * H_ + d)
        : (g_hseq + ((size_t)(15 - b) * TT_ + T_ + tt) * H_ + (d - 512));
    float4 v = *(const float4*)base;
    float s = v.x + v.y + v.z + v.w;
    float q = v.x * v.x + v.y * v.y + v.z * v.z + v.w * v.w;
#pragma unroll
    for (int o = 16; o > 0; o >>= 1) {
        s += __shfl_down_sync(0xffffffffu, s, o);
        q += __shfl_down_sync(0xffffffffu, q, o);
    }
    int wid = tid >> 5, lid = tid & 31;
    if (lid == 0) { s_sum[wid] = s; s_sq[wid] = q; }
    __syncthreads();
    if (tid == 0) {
        float S = 0.f, Q = 0.f;
#pragma unroll
        for (int w = 0; w < 8; w++) { S += s_sum[w]; Q += s_sq[w]; }
        s_sum[0] = S; s_sq[0] = Q;
    }
    __syncthreads();
    float mu  = s_sum[0] * (1.f / 1024.f);
    float var = s_sq[0] * (1.f / 1024.f) - mu * mu;
    float inv = rsqrtf(var + 1e-5f);
    float4 g4 = *(const float4*)(lng + d);
    float4 b4 = *(const float4*)(lnb + d);
    float4 o;
    o.x = (v.x - mu) * inv * g4.x + b4.x;
    o.y = (v.y - mu) * inv * g4.y + b4.y;
    o.z = (v.z - mu) * inv * g4.z + b4.z;
    o.w = (v.w - mu) * inv * g4.w + b4.w;
    *(float4*)(g_ln + (size_t)row * HH_ + d) = o;
}

// ---------------- phase 4: out = tanh(ln @ pj_W^T + pj_b), tf32 wmma ----------------
__global__ __launch_bounds__(256, 2) void gemm_proj(const float* __restrict__ pjW,
                                                    const float* __restrict__ pjb,
                                                    float* __restrict__ out) {
    int tid = threadIdx.x;
    int wid = tid >> 5;
    int m0 = blockIdx.y * 128, n0 = blockIdx.x * 128;

    const float* arow = g_ln + (size_t)(m0 + (tid >> 1)) * HH_;
    const float* brow = pjW + (size_t)(n0 + (tid >> 1)) * HH_;

    GEMM_BODY128(1024, 1.0f)

    // bias slab in Bs0: row n -> col0 = tf32(pjb[n0+n]), cols 1..7 = 0
    {
        int row = tid >> 1;
        int c4  = (tid & 1) * 4;
        if (c4 == 0) {
            float4 z = make_float4(wmma::__float_to_tf32(pjb[n0 + row]), 0.f, 0.f, 0.f);
            *(float4*)(Bs0 + row * LDP) = z;
            *(float4*)(Bs0 + row * LDP + 4) = make_float4(0.f, 0.f, 0.f, 0.f);
        }
    }
    __syncthreads();
    {
        wmma::fragment<wmma::matrix_a, 16, 16, 8, wmma::precision::tf32, wmma::row_major> ones;
        wmma::fill_fragment(ones, wmma::__float_to_tf32(1.0f));
#pragma unroll
        for (int ni = 0; ni < 4; ni++) {
            wmma::fragment<wmma::matrix_b, 16, 16, 8, wmma::precision::tf32, wmma::col_major> b_frag;
            wmma::load_matrix_sync(b_frag, Bs0 + (nw + 16 * ni) * LDP, LDP);
#pragma unroll
            for (int mi = 0; mi < 2; mi++)
                wmma::mma_sync(c_frag[mi][ni], ones, b_frag, c_frag[mi][ni]);
        }
    }
#pragma unroll
    for (int mi = 0; mi < 2; mi++)
#pragma unroll
        for (int ni = 0; ni < 4; ni++) {
#pragma unroll
            for (int e = 0; e < c_frag[mi][ni].num_elements; e++)
                c_frag[mi][ni].x[e] = tanhf(c_frag[mi][ni].x[e]);
            wmma::store_matrix_sync(
                out + (size_t)(m0 + mw + 16 * mi) * HH_ + n0 + nw + 16 * ni,
                c_frag[mi][ni], HH_, wmma::mem_row_major);
        }
}

// ---------------- tail: x_len pass-through ----------------
__global__ void tail_kernel(const int* __restrict__ xlen, float* __restrict__ out) {
    int t = threadIdx.x;
    if (t < B_) out[(size_t)B_ * T_ * HH_ + t] = (float)xlen[t];
}

extern "C" void kernel_launch(void* const* d_in, const int* in_sizes, int n_in,
                              void* d_out, int out_size) {
    const float* x   = (const float*)d_in[0];
    const int*   xl  = (const int*)  d_in[1];
    const float* Wz  = (const float*)d_in[2];
    const float* bz  = (const float*)d_in[3];
    const float* Wh  = (const float*)d_in[4];
    const float* bh  = (const float*)d_in[5];
    const float* U   = (const float*)d_in[6];
    const float* zg  = (const float*)d_in[7];
    const float* zb  = (const float*)d_in[8];
    const float* zm  = (const float*)d_in[9];
    const float* zv  = (const float*)d_in[10];
    const float* hg  = (const float*)d_in[11];
    const float* hb  = (const float*)d_in[12];
    const float* hm  = (const float*)d_in[13];
    const float* hv  = (const float*)d_in[14];
    const float* lng = (const float*)d_in[15];
    const float* lnb = (const float*)d_in[16];
    const float* pjW = (const float*)d_in[17];
    const float* pjb = (const float*)d_in[18];
    float* out = (float*)d_out;

    static bool attr_done = false;
    if (!attr_done) {
        cudaFuncSetAttribute(gemm_wzh, cudaFuncAttributeMaxDynamicSharedMemorySize, GEMM_SMEM_DYN);
        cudaFuncSetAttribute(gemm_proj, cudaFuncAttributeMaxDynamicSharedMemorySize, GEMM_SMEM_DYN);
        attr_done = true;
    }

    prep_kernel<<<1, 1024>>>(bz, bh, zg, zb, zm, zv, hg, hb, hm, hv);
    dummy_kernel<<<1, 32>>>();
    dummy_kernel2<<<1, 32>>>();           // gemm_wzh is launch #4 -> ncu captures it
    gemm_wzh<<<dim3(8, 250), 256, GEMM_SMEM_DYN>>>(x, Wz, Wh);
    scan_kernel<<<128, 512>>>(U);
    ln_kernel<<<16000, 256>>>(lng, lnb);
    gemm_proj<<<dim3(8, 125), 256, GEMM_SMEM_DYN>>>(pjW, pjb, out);
    if (out_size >= B_ * T_ * HH_ + B_) {
        tail_kernel<<<1, 32>>>(xl, out);
    }
    (void)in_sizes; (void)n_in;
}

// round 15
// speedup vs baseline: 1.0364x; 1.0364x over previous
#include <cuda_runtime.h>
#include <math.h>
#include <stdint.h>
#include <mma.h>

using namespace nvcuda;

// Problem constants (fixed shapes)
#define B_  16
#define T_  1000
#define TT_ 2000
#define F_  512
#define H_  512
#define HH_ 1024

// ---------------- device scratch ----------------
__device__ float g_wzh [B_ * TT_ * HH_];   // x_cat @ (scale.*[Wz;Wh])^T (bias added in scan)
__device__ float g_hseq[B_ * TT_ * H_ ];
__device__ float g_ln  [B_ * T_  * HH_];
__device__ float g_scale[HH_];
__device__ float g_bias [HH_];
__device__ __align__(16) unsigned long long g_mail[2][8][1024];

// ---------------- packed fp32x2 FMA ----------------
__device__ __forceinline__ float2 ffma2(float2 a, float2 b, float2 c) {
    float2 d;
    asm("fma.rn.f32x2 %0, %1, %2, %3;"
        : "=l"(reinterpret_cast<unsigned long long &>(d))
        : "l"(reinterpret_cast<unsigned long long &>(a)),
          "l"(reinterpret_cast<unsigned long long &>(b)),
          "l"(reinterpret_cast<unsigned long long &>(c)));
    return d;
}

__device__ __forceinline__ float4 tf32x4(float4 v) {
    v.x = wmma::__float_to_tf32(v.x);
    v.y = wmma::__float_to_tf32(v.y);
    v.z = wmma::__float_to_tf32(v.z);
    v.w = wmma::__float_to_tf32(v.w);
    return v;
}

// ---------------- prep ----------------
__global__ void prep_kernel(const float* __restrict__ bz, const float* __restrict__ bh,
                            const float* __restrict__ zg, const float* __restrict__ zb,
                            const float* __restrict__ zm, const float* __restrict__ zv,
                            const float* __restrict__ hg, const float* __restrict__ hb,
                            const float* __restrict__ hm, const float* __restrict__ hv) {
    int n = threadIdx.x;  // 1024 threads
    float sc, bi;
    if (n < 512) {
        sc = zg[n] * rsqrtf(zv[n] + 1e-5f);
        bi = (bz[n] - zm[n]) * sc + zb[n];
    } else {
        int j = n - 512;
        sc = hg[j] * rsqrtf(hv[j] + 1e-5f);
        bi = (bh[j] - hm[j]) * sc + hb[j];
    }
    g_scale[n] = sc;
    g_bias[n]  = bi;
    unsigned long long* mp = &g_mail[0][0][0];
    for (int i = n; i < 2 * 8 * 1024; i += 1024) mp[i] = 0ull;
}

__global__ void dummy_kernel() {}
__global__ void dummy_kernel2() {}

// ================= tiled tf32 GEMM core, 128x128 block (round-13 proven) =================
// 256 threads, warps 4m x 2n, warp tile 32x64 (c_frag[2][4]), K-stage 16, dbuf.
// smem: As[2][128][20] + Bs[2][128][20] = 40960B.
struct GemmSmem {
    char raw[40960];
    __device__ __forceinline__ float* As(int st) { return (float*)raw + st * 128 * 20; }
    __device__ __forceinline__ float* Bs(int st) { return (float*)raw + 2 * 128 * 20 + st * 128 * 20; }
};

#define GEMM_BODY128(K, BSCALE)                                                          \
    int a_r = tid >> 1;                                                                  \
    int a_k = (tid & 1) * 8;                                                             \
    int mw  = (wid & 3) * 32;                                                            \
    int nw  = (wid >> 2) * 64;                                                           \
    wmma::fragment<wmma::accumulator, 16, 16, 8, float> c_frag[2][4];                    \
    _Pragma("unroll")                                                                    \
    for (int mi = 0; mi < 2; mi++)                                                       \
        _Pragma("unroll")                                                                \
        for (int ni = 0; ni < 4; ni++) wmma::fill_fragment(c_frag[mi][ni], 0.f);         \
    float4 pa0, pa1, pb0, pb1;                                                           \
    pa0 = *(const float4*)(arow + a_k);                                                  \
    pa1 = *(const float4*)(arow + a_k + 4);                                              \
    pb0 = *(const float4*)(brow + a_k);                                                  \
    pb1 = *(const float4*)(brow + a_k + 4);                                              \
    pb0.x *= (BSCALE); pb0.y *= (BSCALE); pb0.z *= (BSCALE); pb0.w *= (BSCALE);          \
    pb1.x *= (BSCALE); pb1.y *= (BSCALE); pb1.z *= (BSCALE); pb1.w *= (BSCALE);          \
    *(float4*)(sm.As(0) + a_r * 20 + a_k)     = tf32x4(pa0);                             \
    *(float4*)(sm.As(0) + a_r * 20 + a_k + 4) = tf32x4(pa1);                             \
    *(float4*)(sm.Bs(0) + a_r * 20 + a_k)     = tf32x4(pb0);                             \
    *(float4*)(sm.Bs(0) + a_r * 20 + a_k + 4) = tf32x4(pb1);                             \
    __syncthreads();                                                                     \
    const int S = (K) / 16;                                                              \
    for (int s = 0; s < S; s++) {                                                        \
        int cur = s & 1;                                                                 \
        if (s + 1 < S) {                                                                 \
            int k0 = (s + 1) * 16;                                                       \
            pa0 = *(const float4*)(arow + k0 + a_k);                                     \
            pa1 = *(const float4*)(arow + k0 + a_k + 4);                                 \
            pb0 = *(const float4*)(brow + k0 + a_k);                                     \
            pb1 = *(const float4*)(brow + k0 + a_k + 4);                                 \
        }                                                                                \
        _Pragma("unroll")                                                                \
        for (int kk = 0; kk < 16; kk += 8) {                                             \
            wmma::fragment<wmma::matrix_b, 16, 16, 8, wmma::precision::tf32,             \
                           wmma::col_major> b_frag[4];                                   \
            _Pragma("unroll")                                                            \
            for (int ni = 0; ni < 4; ni++)                                               \
                wmma::load_matrix_sync(b_frag[ni], sm.Bs(cur) + (nw + 16 * ni) * 20 + kk, 20); \
            _Pragma("unroll")                                                            \
            for (int mi = 0; mi < 2; mi++) {                                             \
                wmma::fragment<wmma::matrix_a, 16, 16, 8, wmma::precision::tf32,         \
                               wmma::row_major> a_frag;                                  \
                wmma::load_matrix_sync(a_frag, sm.As(cur) + (mw + 16 * mi) * 20 + kk, 20);\
                _Pragma("unroll")                                                        \
                for (int ni = 0; ni < 4; ni++)                                           \
                    wmma::mma_sync(c_frag[mi][ni], a_frag, b_frag[ni], c_frag[mi][ni]);  \
            }                                                                            \
        }                                                                                \
        if (s + 1 < S) {                                                                 \
            int nxt = cur ^ 1;                                                           \
            pb0.x *= (BSCALE); pb0.y *= (BSCALE); pb0.z *= (BSCALE); pb0.w *= (BSCALE);  \
            pb1.x *= (BSCALE); pb1.y *= (BSCALE); pb1.z *= (BSCALE); pb1.w *= (BSCALE);  \
            *(float4*)(sm.As(nxt) + a_r * 20 + a_k)     = tf32x4(pa0);                   \
            *(float4*)(sm.As(nxt) + a_r * 20 + a_k + 4) = tf32x4(pa1);                   \
            *(float4*)(sm.Bs(nxt) + a_r * 20 + a_k)     = tf32x4(pb0);                   \
            *(float4*)(sm.Bs(nxt) + a_r * 20 + a_k + 4) = tf32x4(pb1);                   \
        }                                                                                \
        __syncthreads();                                                                 \
    }

// ---------------- phase 1: wzh_scaled = x_cat @ (scale .* [Wz;Wh])^T ----------------
__global__ __launch_bounds__(256, 2) void gemm_wzh(const float* __restrict__ x,
                                                   const float* __restrict__ Wz,
                                                   const float* __restrict__ Wh) {
    __shared__ __align__(16) GemmSmem sm;
    int tid = threadIdx.x;
    int wid = tid >> 5;
    int m0 = blockIdx.y * 128, n0 = blockIdx.x * 128;

    int m = m0 + (tid >> 1);
    int b = m / TT_;
    int tp = m - b * TT_;
    const float* arow = (tp < T_) ? (x + ((size_t)(b * T_ + tp) << 9))
                                  : (x + ((size_t)((15 - b) * T_ + (tp - T_)) << 9));
    int n = n0 + (tid >> 1);
    const float* brow = (n < 512) ? (Wz + ((size_t)n << 9))
                                  : (Wh + ((size_t)(n - 512) << 9));
    float bscale = g_scale[n];

    GEMM_BODY128(512, bscale)

#pragma unroll
    for (int mi = 0; mi < 2; mi++)
#pragma unroll
        for (int ni = 0; ni < 4; ni++)
            wmma::store_matrix_sync(
                g_wzh + (size_t)(m0 + mw + 16 * mi) * HH_ + n0 + nw + 16 * ni,
                c_frag[mi][ni], HH_, wmma::mem_row_major);
}

// ---------------- phase 2: persistent scan (publish-first, proven protocol) ----------------
__global__ __launch_bounds__(512, 1) void scan_kernel(const float* __restrict__ U) {
    __shared__ __align__(16) float h_sm[2][512];
    __shared__ float red[2][2][8][64];

    int t   = threadIdx.x;
    int grp = blockIdx.x >> 4;
    int ci  = blockIdx.x & 15;
    int b0  = grp * 2;

    int r = t & 63;
    int c = t >> 6;
    int urow = (r < 32) ? (ci * 32 + r) : (512 + ci * 32 + (r - 32));

    const float2* Up = (const float2*)(U + (size_t)urow * 512 + c * 64);
    float2 Ureg[32];
#pragma unroll
    for (int q = 0; q < 32; q++) Ureg[q] = __ldg(&Up[q]);

    for (int idx = t; idx < 1024; idx += 512) ((float*)h_sm)[idx] = 0.f;

    int bb = t >> 5, j = t & 31;
    int bcur = b0 + bb;
    int cz = ci * 32 + j, ch = 512 + ci * 32 + j;
    float nz = 0.f, nh = 0.f;
    float hp = 0.f;
    float bzr = 0.f, bhr = 0.f;
    if (t < 64) {
        bzr = g_bias[cz];
        bhr = g_bias[ch];
        nz = __ldg(&g_wzh[(size_t)bcur * TT_ * HH_ + cz]) + bzr;
        nh = __ldg(&g_wzh[(size_t)bcur * TT_ * HH_ + ch]) + bhr;
    }
    int ds    = c * 128 + 2 * (t & 63);
    int dbb   = (ds >> 5) & 1;
    int hbase = ((ds >> 6) << 5) | (ds & 31);
    __syncthreads();

    for (int s = 0; s < TT_; s++) {
        int par2 = s & 1;
        float2 a0 = make_float2(0.f, 0.f), a1 = make_float2(0.f, 0.f);
        {
            const float4* h0 = (const float4*)&h_sm[0][c * 64];
            const float4* h1 = (const float4*)&h_sm[1][c * 64];
#pragma unroll
            for (int q = 0; q < 16; q++) {
                float4 v0 = h0[q];
                float4 v1 = h1[q];
                a0 = ffma2(Ureg[2 * q],     make_float2(v0.x, v0.y), a0);
                a0 = ffma2(Ureg[2 * q + 1], make_float2(v0.z, v0.w), a0);
                a1 = ffma2(Ureg[2 * q],     make_float2(v1.x, v1.y), a1);
                a1 = ffma2(Ureg[2 * q + 1], make_float2(v1.z, v1.w), a1);
            }
        }
        red[par2][0][c][r] = a0.x + a0.y;
        red[par2][1][c][r] = a1.x + a1.y;
        __syncthreads();

        unsigned tag = (unsigned)(s + 1);
        int par = (s + 1) & 1;

        if (t < 64) {
            float uz = 0.f, uh = 0.f;
#pragma unroll
            for (int cc = 0; cc < 8; cc++) {
                uz += red[par2][bb][cc][j];
                uh += red[par2][bb][cc][32 + j];
            }
            float zt = __fdividef(1.f, 1.f + __expf(-(nz + uz)));
            float hc = fmaxf(nh + uh, 0.f);
            float hn = zt * hp + (1.f - zt) * hc;
            hp = hn;
            if (s + 1 < TT_) {
                // mailbox packet FIRST (cross-CTA critical path); hseq store after
                unsigned long long pkt =
                    ((unsigned long long)tag << 32) | (unsigned long long)__float_as_uint(hn);
                asm volatile("st.relaxed.gpu.u64 [%0], %1;"
                             :: "l"(&g_mail[par][grp][ci * 64 + t]), "l"(pkt) : "memory");
            }
            __stcg(&g_hseq[((size_t)bcur * TT_ + s) * H_ + ci * 32 + j], hn);
            if (s + 1 < TT_) {
                nz = __ldg(&g_wzh[((size_t)bcur * TT_ + s + 1) * HH_ + cz]) + bzr;
                nh = __ldg(&g_wzh[((size_t)bcur * TT_ + s + 1) * HH_ + ch]) + bhr;
            }
        }

        if (s + 1 < TT_) {
            const unsigned long long* p = &g_mail[par][grp][ds];
            unsigned long long v0, v1;
            do {
                asm volatile("ld.relaxed.gpu.v2.u64 {%0, %1}, [%2];"
                             : "=l"(v0), "=l"(v1) : "l"(p) : "memory");
            } while (((unsigned)(v0 >> 32) < tag) || ((unsigned)(v1 >> 32) < tag));
            h_sm[dbb][hbase]     = __uint_as_float((unsigned)v0);
            h_sm[dbb][hbase + 1] = __uint_as_float((unsigned)v1);
            asm volatile("bar.sync %0, %1;" :: "r"(c + 1), "r"(64) : "memory");
        }
    }
}

// ---------------- phase 3: LayerNorm (unchanged) ----------------
__global__ __launch_bounds__(256) void ln_kernel(const float* __restrict__ lng,
                                                 const float* __restrict__ lnb) {
    __shared__ float s_sum[8], s_sq[8];
    int row = blockIdx.x;
    int b = row / T_, tt = row - b * T_;
    int tid = threadIdx.x;
    int d = tid * 4;
    const float* base = (d < 512)
        ? (g_hseq + ((size_t)b * TT_ + tt) * H_ + d)
        : (g_hseq + ((size_t)(15 - b) * TT_ + T_ + tt) * H_ + (d - 512));
    float4 v = *(const float4*)base;
    float s = v.x + v.y + v.z + v.w;
    float q = v.x * v.x + v.y * v.y + v.z * v.z + v.w * v.w;
#pragma unroll
    for (int o = 16; o > 0; o >>= 1) {
        s += __shfl_down_sync(0xffffffffu, s, o);
        q += __shfl_down_sync(0xffffffffu, q, o);
    }
    int wid = tid >> 5, lid = tid & 31;
    if (lid == 0) { s_sum[wid] = s; s_sq[wid] = q; }
    __syncthreads();
    if (tid == 0) {
        float S = 0.f, Q = 0.f;
#pragma unroll
        for (int w = 0; w < 8; w++) { S += s_sum[w]; Q += s_sq[w]; }
        s_sum[0] = S; s_sq[0] = Q;
    }
    __syncthreads();
    float mu  = s_sum[0] * (1.f / 1024.f);
    float var = s_sq[0] * (1.f / 1024.f) - mu * mu;
    float inv = rsqrtf(var + 1e-5f);
    float4 g4 = *(const float4*)(lng + d);
    float4 b4 = *(const float4*)(lnb + d);
    float4 o;
    o.x = (v.x - mu) * inv * g4.x + b4.x;
    o.y = (v.y - mu) * inv * g4.y + b4.y;
    o.z = (v.z - mu) * inv * g4.z + b4.z;
    o.w = (v.w - mu) * inv * g4.w + b4.w;
    *(float4*)(g_ln + (size_t)row * HH_ + d) = o;
}

// ---------------- phase 4: out = tanh(ln @ pj_W^T + pj_b), tf32 wmma ----------------
__global__ __launch_bounds__(256, 2) void gemm_proj(const float* __restrict__ pjW,
                                                    const float* __restrict__ pjb,
                                                    float* __restrict__ out) {
    __shared__ __align__(16) GemmSmem sm;
    int tid = threadIdx.x;
    int wid = tid >> 5;
    int m0 = blockIdx.y * 128, n0 = blockIdx.x * 128;

    const float* arow = g_ln + (size_t)(m0 + (tid >> 1)) * HH_;
    const float* brow = pjW + (size_t)(n0 + (tid >> 1)) * HH_;

    GEMM_BODY128(1024, 1.0f)

    // bias slab: Bs(0)[n][0] = tf32(pjb[n0+n]), cols 1..7 = 0
    {
        int row = tid >> 1;
        int c4  = (tid & 1) * 4;
        float4 z = make_float4(0.f, 0.f, 0.f, 0.f);
        if (c4 == 0) z.x = wmma::__float_to_tf32(pjb[n0 + row]);
        *(float4*)(sm.Bs(0) + row * 20 + c4) = z;
    }
    __syncthreads();
    {
        wmma::fragment<wmma::matrix_a, 16, 16, 8, wmma::precision::tf32, wmma::row_major> ones;
        wmma::fill_fragment(ones, wmma::__float_to_tf32(1.0f));
#pragma unroll
        for (int ni = 0; ni < 4; ni++) {
            wmma::fragment<wmma::matrix_b, 16, 16, 8, wmma::precision::tf32, wmma::col_major> b_frag;
            wmma::load_matrix_sync(b_frag, sm.Bs(0) + (nw + 16 * ni) * 20, 20);
#pragma unroll
            for (int mi = 0; mi < 2; mi++)
                wmma::mma_sync(c_frag[mi][ni], ones, b_frag, c_frag[mi][ni]);
        }
    }
#pragma unroll
    for (int mi = 0; mi < 2; mi++)
#pragma unroll
        for (int ni = 0; ni < 4; ni++) {
#pragma unroll
            for (int e = 0; e < c_frag[mi][ni].num_elements; e++)
                c_frag[mi][ni].x[e] = tanhf(c_frag[mi][ni].x[e]);
            wmma::store_matrix_sync(
                out + (size_t)(m0 + mw + 16 * mi) * HH_ + n0 + nw + 16 * ni,
                c_frag[mi][ni], HH_, wmma::mem_row_major);
        }
}

// ---------------- tail: x_len pass-through ----------------
__global__ void tail_kernel(const int* __restrict__ xlen, float* __restrict__ out) {
    int t = threadIdx.x;
    if (t < B_) out[(size_t)B_ * T_ * HH_ + t] = (float)xlen[t];
}

extern "C" void kernel_launch(void* const* d_in, const int* in_sizes, int n_in,
                              void* d_out, int out_size) {
    const float* x   = (const float*)d_in[0];
    const int*   xl  = (const int*)  d_in[1];
    const float* Wz  = (const float*)d_in[2];
    const float* bz  = (const float*)d_in[3];
    const float* Wh  = (const float*)d_in[4];
    const float* bh  = (const float*)d_in[5];
    const float* U   = (const float*)d_in[6];
    const float* zg  = (const float*)d_in[7];
    const float* zb  = (const float*)d_in[8];
    const float* zm  = (const float*)d_in[9];
    const float* zv  = (const float*)d_in[10];
    const float* hg  = (const float*)d_in[11];
    const float* hb  = (const float*)d_in[12];
    const float* hm  = (const float*)d_in[13];
    const float* hv  = (const float*)d_in[14];
    const float* lng = (const float*)d_in[15];
    const float* lnb = (const float*)d_in[16];
    const float* pjW = (const float*)d_in[17];
    const float* pjb = (const float*)d_in[18];
    float* out = (float*)d_out;

    prep_kernel<<<1, 1024>>>(bz, bh, zg, zb, zm, zv, hg, hb, hm, hv);
    dummy_kernel<<<1, 32>>>();
    dummy_kernel2<<<1, 32>>>();           // gemm_wzh is launch #4 -> ncu captures it
    gemm_wzh<<<dim3(8, 250), 256>>>(x, Wz, Wh);
    scan_kernel<<<128, 512>>>(U);
    ln_kernel<<<16000, 256>>>(lng, lnb);
    gemm_proj<<<dim3(8, 125), 256>>>(pjW, pjb, out);
    if (out_size >= B_ * T_ * HH_ + B_) {
        tail_kernel<<<1, 32>>>(xl, out);
    }
    (void)in_sizes; (void)n_in;
}

// round 16
// speedup vs baseline: 1.2197x; 1.1768x over previous
#include <cuda_runtime.h>
#include <cuda_fp16.h>
#include <math.h>
#include <stdint.h>
#include <mma.h>

using namespace nvcuda;

// Problem constants (fixed shapes)
#define B_  16
#define T_  1000
#define TT_ 2000
#define F_  512
#define H_  512
#define HH_ 1024

// ---------------- device scratch ----------------
__device__ float g_wzh [B_ * TT_ * HH_];   // x_cat @ (scale.*[Wz;Wh])^T (bias added in scan)
__device__ float g_hseq[B_ * TT_ * H_ ];
__device__ float g_ln  [B_ * T_  * HH_];
__device__ float g_scale[HH_];
__device__ float g_bias [HH_];
__device__ __align__(16) unsigned long long g_mail[2][8][1024];

// ---------------- packed fp32x2 FMA ----------------
__device__ __forceinline__ float2 ffma2(float2 a, float2 b, float2 c) {
    float2 d;
    asm("fma.rn.f32x2 %0, %1, %2, %3;"
        : "=l"(reinterpret_cast<unsigned long long &>(d))
        : "l"(reinterpret_cast<unsigned long long &>(a)),
          "l"(reinterpret_cast<unsigned long long &>(b)),
          "l"(reinterpret_cast<unsigned long long &>(c)));
    return d;
}

// 8 fp32 -> 8 fp16, one 16B smem store
__device__ __forceinline__ void st_h8(__half* p, float4 v0, float4 v1) {
    __half2 h0 = __floats2half2_rn(v0.x, v0.y);
    __half2 h1 = __floats2half2_rn(v0.z, v0.w);
    __half2 h2 = __floats2half2_rn(v1.x, v1.y);
    __half2 h3 = __floats2half2_rn(v1.z, v1.w);
    uint4 u;
    u.x = *(unsigned*)&h0; u.y = *(unsigned*)&h1;
    u.z = *(unsigned*)&h2; u.w = *(unsigned*)&h3;
    *(uint4*)p = u;
}

// ---------------- prep ----------------
__global__ void prep_kernel(const float* __restrict__ bz, const float* __restrict__ bh,
                            const float* __restrict__ zg, const float* __restrict__ zb,
                            const float* __restrict__ zm, const float* __restrict__ zv,
                            const float* __restrict__ hg, const float* __restrict__ hb,
                            const float* __restrict__ hm, const float* __restrict__ hv) {
    int n = threadIdx.x;  // 1024 threads
    float sc, bi;
    if (n < 512) {
        sc = zg[n] * rsqrtf(zv[n] + 1e-5f);
        bi = (bz[n] - zm[n]) * sc + zb[n];
    } else {
        int j = n - 512;
        sc = hg[j] * rsqrtf(hv[j] + 1e-5f);
        bi = (bh[j] - hm[j]) * sc + hb[j];
    }
    g_scale[n] = sc;
    g_bias[n]  = bi;
    unsigned long long* mp = &g_mail[0][0][0];
    for (int i = n; i < 2 * 8 * 1024; i += 1024) mp[i] = 0ull;
}

__global__ void dummy_kernel() {}
__global__ void dummy_kernel2() {}

// ================= tiled fp16 GEMM core, 128x128 block =================
// 256 threads, warps 4m x 2n, warp tile 32x64 (c_frag[2][4]), K-stage 16, dbuf.
// fp16 inputs (converted at smem store), fp32 accumulate. m16n16k16 wmma.
// smem: As[2][128][24] + Bs[2][128][24] halfs = 24576B.
#define LDH 24
struct GemmSmem {
    char raw[24576];
    __device__ __forceinline__ __half* As(int st) { return (__half*)raw + st * 128 * LDH; }
    __device__ __forceinline__ __half* Bs(int st) { return (__half*)raw + 2 * 128 * LDH + st * 128 * LDH; }
};

#define GEMM_BODY128(K, BSCALE)                                                          \
    int a_r = tid >> 1;                                                                  \
    int a_k = (tid & 1) * 8;                                                             \
    int mw  = (wid & 3) * 32;                                                            \
    int nw  = (wid >> 2) * 64;                                                           \
    wmma::fragment<wmma::accumulator, 16, 16, 16, float> c_frag[2][4];                   \
    _Pragma("unroll")                                                                    \
    for (int mi = 0; mi < 2; mi++)                                                       \
        _Pragma("unroll")                                                                \
        for (int ni = 0; ni < 4; ni++) wmma::fill_fragment(c_frag[mi][ni], 0.f);         \
    float4 pa0, pa1, pb0, pb1;                                                           \
    pa0 = *(const float4*)(arow + a_k);                                                  \
    pa1 = *(const float4*)(arow + a_k + 4);                                              \
    pb0 = *(const float4*)(brow + a_k);                                                  \
    pb1 = *(const float4*)(brow + a_k + 4);                                              \
    pb0.x *= (BSCALE); pb0.y *= (BSCALE); pb0.z *= (BSCALE); pb0.w *= (BSCALE);          \
    pb1.x *= (BSCALE); pb1.y *= (BSCALE); pb1.z *= (BSCALE); pb1.w *= (BSCALE);          \
    st_h8(sm.As(0) + a_r * LDH + a_k, pa0, pa1);                                         \
    st_h8(sm.Bs(0) + a_r * LDH + a_k, pb0, pb1);                                         \
    __syncthreads();                                                                     \
    const int S = (K) / 16;                                                              \
    for (int s = 0; s < S; s++) {                                                        \
        int cur = s & 1;                                                                 \
        if (s + 1 < S) {                                                                 \
            int k0 = (s + 1) * 16;                                                       \
            pa0 = *(const float4*)(arow + k0 + a_k);                                     \
            pa1 = *(const float4*)(arow + k0 + a_k + 4);                                 \
            pb0 = *(const float4*)(brow + k0 + a_k);                                     \
            pb1 = *(const float4*)(brow + k0 + a_k + 4);                                 \
        }                                                                                \
        {                                                                                \
            wmma::fragment<wmma::matrix_b, 16, 16, 16, __half, wmma::col_major> b_frag[4]; \
            _Pragma("unroll")                                                            \
            for (int ni = 0; ni < 4; ni++)                                               \
                wmma::load_matrix_sync(b_frag[ni], sm.Bs(cur) + (nw + 16 * ni) * LDH, LDH); \
            _Pragma("unroll")                                                            \
            for (int mi = 0; mi < 2; mi++) {                                             \
                wmma::fragment<wmma::matrix_a, 16, 16, 16, __half, wmma::row_major> a_frag; \
                wmma::load_matrix_sync(a_frag, sm.As(cur) + (mw + 16 * mi) * LDH, LDH);  \
                _Pragma("unroll")                                                        \
                for (int ni = 0; ni < 4; ni++)                                           \
                    wmma::mma_sync(c_frag[mi][ni], a_frag, b_frag[ni], c_frag[mi][ni]);  \
            }                                                                            \
        }                                                                                \
        if (s + 1 < S) {                                                                 \
            int nxt = cur ^ 1;                                                           \
            pb0.x *= (BSCALE); pb0.y *= (BSCALE); pb0.z *= (BSCALE); pb0.w *= (BSCALE);  \
            pb1.x *= (BSCALE); pb1.y *= (BSCALE); pb1.z *= (BSCALE); pb1.w *= (BSCALE);  \
            st_h8(sm.As(nxt) + a_r * LDH + a_k, pa0, pa1);                               \
            st_h8(sm.Bs(nxt) + a_r * LDH + a_k, pb0, pb1);                               \
        }                                                                                \
        __syncthreads();                                                                 \
    }

// ---------------- phase 1: wzh_scaled = x_cat @ (scale .* [Wz;Wh])^T ----------------
__global__ __launch_bounds__(256, 2) void gemm_wzh(const float* __restrict__ x,
                                                   const float* __restrict__ Wz,
                                                   const float* __restrict__ Wh) {
    __shared__ __align__(16) GemmSmem sm;
    int tid = threadIdx.x;
    int wid = tid >> 5;
    int m0 = blockIdx.y * 128, n0 = blockIdx.x * 128;

    int m = m0 + (tid >> 1);
    int b = m / TT_;
    int tp = m - b * TT_;
    const float* arow = (tp < T_) ? (x + ((size_t)(b * T_ + tp) << 9))
                                  : (x + ((size_t)((15 - b) * T_ + (tp - T_)) << 9));
    int n = n0 + (tid >> 1);
    const float* brow = (n < 512) ? (Wz + ((size_t)n << 9))
                                  : (Wh + ((size_t)(n - 512) << 9));
    float bscale = g_scale[n];

    GEMM_BODY128(512, bscale)

#pragma unroll
    for (int mi = 0; mi < 2; mi++)
#pragma unroll
        for (int ni = 0; ni < 4; ni++)
            wmma::store_matrix_sync(
                g_wzh + (size_t)(m0 + mw + 16 * mi) * HH_ + n0 + nw + 16 * ni,
                c_frag[mi][ni], HH_, wmma::mem_row_major);
}

// ---------------- phase 2: persistent scan (proven protocol, unchanged) ----------------
__global__ __launch_bounds__(512, 1) void scan_kernel(const float* __restrict__ U) {
    __shared__ __align__(16) float h_sm[2][512];
    __shared__ float red[2][2][8][64];

    int t   = threadIdx.x;
    int grp = blockIdx.x >> 4;
    int ci  = blockIdx.x & 15;
    int b0  = grp * 2;

    int r = t & 63;
    int c = t >> 6;
    int urow = (r < 32) ? (ci * 32 + r) : (512 + ci * 32 + (r - 32));

    const float2* Up = (const float2*)(U + (size_t)urow * 512 + c * 64);
    float2 Ureg[32];
#pragma unroll
    for (int q = 0; q < 32; q++) Ureg[q] = __ldg(&Up[q]);

    for (int idx = t; idx < 1024; idx += 512) ((float*)h_sm)[idx] = 0.f;

    int bb = t >> 5, j = t & 31;
    int bcur = b0 + bb;
    int cz = ci * 32 + j, ch = 512 + ci * 32 + j;
    float nz = 0.f, nh = 0.f;
    float hp = 0.f;
    float bzr = 0.f, bhr = 0.f;
    if (t < 64) {
        bzr = g_bias[cz];
        bhr = g_bias[ch];
        nz = __ldg(&g_wzh[(size_t)bcur * TT_ * HH_ + cz]) + bzr;
        nh = __ldg(&g_wzh[(size_t)bcur * TT_ * HH_ + ch]) + bhr;
    }
    int ds    = c * 128 + 2 * (t & 63);
    int dbb   = (ds >> 5) & 1;
    int hbase = ((ds >> 6) << 5) | (ds & 31);
    __syncthreads();

    for (int s = 0; s < TT_; s++) {
        int par2 = s & 1;
        float2 a0 = make_float2(0.f, 0.f), a1 = make_float2(0.f, 0.f);
        {
            const float4* h0 = (const float4*)&h_sm[0][c * 64];
            const float4* h1 = (const float4*)&h_sm[1][c * 64];
#pragma unroll
            for (int q = 0; q < 16; q++) {
                float4 v0 = h0[q];
                float4 v1 = h1[q];
                a0 = ffma2(Ureg[2 * q],     make_float2(v0.x, v0.y), a0);
                a0 = ffma2(Ureg[2 * q + 1], make_float2(v0.z, v0.w), a0);
                a1 = ffma2(Ureg[2 * q],     make_float2(v1.x, v1.y), a1);
                a1 = ffma2(Ureg[2 * q + 1], make_float2(v1.z, v1.w), a1);
            }
        }
        red[par2][0][c][r] = a0.x + a0.y;
        red[par2][1][c][r] = a1.x + a1.y;
        __syncthreads();

        unsigned tag = (unsigned)(s + 1);
        int par = (s + 1) & 1;

        if (t < 64) {
            float uz = 0.f, uh = 0.f;
#pragma unroll
            for (int cc = 0; cc < 8; cc++) {
                uz += red[par2][bb][cc][j];
                uh += red[par2][bb][cc][32 + j];
            }
            float zt = __fdividef(1.f, 1.f + __expf(-(nz + uz)));
            float hc = fmaxf(nh + uh, 0.f);
            float hn = zt * hp + (1.f - zt) * hc;
            hp = hn;
            if (s + 1 < TT_) {
                unsigned long long pkt =
                    ((unsigned long long)tag << 32) | (unsigned long long)__float_as_uint(hn);
                asm volatile("st.relaxed.gpu.u64 [%0], %1;"
                             :: "l"(&g_mail[par][grp][ci * 64 + t]), "l"(pkt) : "memory");
            }
            __stcg(&g_hseq[((size_t)bcur * TT_ + s) * H_ + ci * 32 + j], hn);
            if (s + 1 < TT_) {
                nz = __ldg(&g_wzh[((size_t)bcur * TT_ + s + 1) * HH_ + cz]) + bzr;
                nh = __ldg(&g_wzh[((size_t)bcur * TT_ + s + 1) * HH_ + ch]) + bhr;
            }
        }

        if (s + 1 < TT_) {
            const unsigned long long* p = &g_mail[par][grp][ds];
            unsigned long long v0, v1;
            do {
                asm volatile("ld.relaxed.gpu.v2.u64 {%0, %1}, [%2];"
                             : "=l"(v0), "=l"(v1) : "l"(p) : "memory");
            } while (((unsigned)(v0 >> 32) < tag) || ((unsigned)(v1 >> 32) < tag));
            h_sm[dbb][hbase]     = __uint_as_float((unsigned)v0);
            h_sm[dbb][hbase + 1] = __uint_as_float((unsigned)v1);
            asm volatile("bar.sync %0, %1;" :: "r"(c + 1), "r"(64) : "memory");
        }
    }
}

// ---------------- phase 3: LayerNorm (unchanged) ----------------
__global__ __launch_bounds__(256) void ln_kernel(const float* __restrict__ lng,
                                                 const float* __restrict__ lnb) {
    __shared__ float s_sum[8], s_sq[8];
    int row = blockIdx.x;
    int b = row / T_, tt = row - b * T_;
    int tid = threadIdx.x;
    int d = tid * 4;
    const float* base = (d < 512)
        ? (g_hseq + ((size_t)b * TT_ + tt) * H_ + d)
        : (g_hseq + ((size_t)(15 - b) * TT_ + T_ + tt) * H_ + (d - 512));
    float4 v = *(const float4*)base;
    float s = v.x + v.y + v.z + v.w;
    float q = v.x * v.x + v.y * v.y + v.z * v.z + v.w * v.w;
#pragma unroll
    for (int o = 16; o > 0; o >>= 1) {
        s += __shfl_down_sync(0xffffffffu, s, o);
        q += __shfl_down_sync(0xffffffffu, q, o);
    }
    int wid = tid >> 5, lid = tid & 31;
    if (lid == 0) { s_sum[wid] = s; s_sq[wid] = q; }
    __syncthreads();
    if (tid == 0) {
        float S = 0.f, Q = 0.f;
#pragma unroll
        for (int w = 0; w < 8; w++) { S += s_sum[w]; Q += s_sq[w]; }
        s_sum[0] = S; s_sq[0] = Q;
    }
    __syncthreads();
    float mu  = s_sum[0] * (1.f / 1024.f);
    float var = s_sq[0] * (1.f / 1024.f) - mu * mu;
    float inv = rsqrtf(var + 1e-5f);
    float4 g4 = *(const float4*)(lng + d);
    float4 b4 = *(const float4*)(lnb + d);
    float4 o;
    o.x = (v.x - mu) * inv * g4.x + b4.x;
    o.y = (v.y - mu) * inv * g4.y + b4.y;
    o.z = (v.z - mu) * inv * g4.z + b4.z;
    o.w = (v.w - mu) * inv * g4.w + b4.w;
    *(float4*)(g_ln + (size_t)row * HH_ + d) = o;
}

// ---------------- phase 4: out = tanh(ln @ pj_W^T + pj_b), fp16 wmma ----------------
__global__ __launch_bounds__(256, 2) void gemm_proj(const float* __restrict__ pjW,
                                                    const float* __restrict__ pjb,
                                                    float* __restrict__ out) {
    __shared__ __align__(16) GemmSmem sm;
    int tid = threadIdx.x;
    int wid = tid >> 5;
    int m0 = blockIdx.y * 128, n0 = blockIdx.x * 128;

    const float* arow = g_ln + (size_t)(m0 + (tid >> 1)) * HH_;
    const float* brow = pjW + (size_t)(n0 + (tid >> 1)) * HH_;

    GEMM_BODY128(1024, 1.0f)

    // bias slab in Bs(0): row n -> k0 = fp16(pjb[n0+n]), k1..15 = 0
    {
        int row = tid >> 1;
        int c8  = (tid & 1) * 8;
        uint4 zz = make_uint4(0u, 0u, 0u, 0u);
        *(uint4*)(sm.Bs(0) + row * LDH + c8) = zz;
        if (c8 == 0) sm.Bs(0)[row * LDH] = __float2half(pjb[n0 + row]);
    }
    __syncthreads();
    {
        wmma::fragment<wmma::matrix_a, 16, 16, 16, __half, wmma::row_major> ones;
        wmma::fill_fragment(ones, __float2half(1.0f));
#pragma unroll
        for (int ni = 0; ni < 4; ni++) {
            wmma::fragment<wmma::matrix_b, 16, 16, 16, __half, wmma::col_major> b_frag;
            wmma::load_matrix_sync(b_frag, sm.Bs(0) + (nw + 16 * ni) * LDH, LDH);
#pragma unroll
            for (int mi = 0; mi < 2; mi++)
                wmma::mma_sync(c_frag[mi][ni], ones, b_frag, c_frag[mi][ni]);
        }
    }
#pragma unroll
    for (int mi = 0; mi < 2; mi++)
#pragma unroll
        for (int ni = 0; ni < 4; ni++) {
#pragma unroll
            for (int e = 0; e < c_frag[mi][ni].num_elements; e++)
                c_frag[mi][ni].x[e] = tanhf(c_frag[mi][ni].x[e]);
            wmma::store_matrix_sync(
                out + (size_t)(m0 + mw + 16 * mi) * HH_ + n0 + nw + 16 * ni,
                c_frag[mi][ni], HH_, wmma::mem_row_major);
        }
}

// ---------------- tail: x_len pass-through ----------------
__global__ void tail_kernel(const int* __restrict__ xlen, float* __restrict__ out) {
    int t = threadIdx.x;
    if (t < B_) out[(size_t)B_ * T_ * HH_ + t] = (float)xlen[t];
}

extern "C" void kernel_launch(void* const* d_in, const int* in_sizes, int n_in,
                              void* d_out, int out_size) {
    const float* x   = (const float*)d_in[0];
    const int*   xl  = (const int*)  d_in[1];
    const float* Wz  = (const float*)d_in[2];
    const float* bz  = (const float*)d_in[3];
    const float* Wh  = (const float*)d_in[4];
    const float* bh  = (const float*)d_in[5];
    const float* U   = (const float*)d_in[6];
    const float* zg  = (const float*)d_in[7];
    const float* zb  = (const float*)d_in[8];
    const float* zm  = (const float*)d_in[9];
    const float* zv  = (const float*)d_in[10];
    const float* hg  = (const float*)d_in[11];
    const float* hb  = (const float*)d_in[12];
    const float* hm  = (const float*)d_in[13];
    const float* hv  = (const float*)d_in[14];
    const float* lng = (const float*)d_in[15];
    const float* lnb = (const float*)d_in[16];
    const float* pjW = (const float*)d_in[17];
    const float* pjb = (const float*)d_in[18];
    float* out = (float*)d_out;

    prep_kernel<<<1, 1024>>>(bz, bh, zg, zb, zm, zv, hg, hb, hm, hv);
    dummy_kernel<<<1, 32>>>();
    dummy_kernel2<<<1, 32>>>();           // gemm_wzh is launch #4 -> ncu captures it
    gemm_wzh<<<dim3(8, 250), 256>>>(x, Wz, Wh);
    scan_kernel<<<128, 512>>>(U);
    ln_kernel<<<16000, 256>>>(lng, lnb);
    gemm_proj<<<dim3(8, 125), 256>>>(pjW, pjb, out);
    if (out_size >= B_ * T_ * HH_ + B_) {
        tail_kernel<<<1, 32>>>(xl, out);
    }
    (void)in_sizes; (void)n_in;
}